// round 3
// baseline (speedup 1.0000x reference)
#include <cuda_runtime.h>
#include <cuda_bf16.h>
#include <math.h>

// Problem dims (fixed by the reference)
#define BB   64
#define NN   512
#define MD   1024
#define AD   1024
#define ROWS (BB * NN)   // 32768 flattened (b, n) rows

// Scratch (allocation-free rule: __device__ globals)
__device__ float g_tq[BB * AD];       // query @ Ws
__device__ float g_logits[ROWS];      // tanh(mv@Wh + tq) @ v
__device__ float g_weights[ROWS];     // softmax weights

// ---------------------------------------------------------------------------
// Zero init for atomically-accumulated buffers (+ d_out, which is poisoned)
// ---------------------------------------------------------------------------
__global__ void zero_kernel(float* __restrict__ ctx) {
    int i = blockIdx.x * blockDim.x + threadIdx.x;
    if (i < ROWS) g_logits[i] = 0.0f;
    if (i < BB * AD) ctx[i] = 0.0f;
}

// ---------------------------------------------------------------------------
// tq = query @ Ws.  One block per batch row; Ws columns read coalesced.
// ---------------------------------------------------------------------------
__global__ __launch_bounds__(256) void tq_kernel(const float* __restrict__ q,
                                                 const float* __restrict__ Ws) {
    __shared__ float qs[MD];
    int b = blockIdx.x;
    for (int i = threadIdx.x; i < MD; i += 256) qs[i] = q[b * MD + i];
    __syncthreads();

    int a0 = threadIdx.x;               // handles a0, a0+256, a0+512, a0+768
    float acc0 = 0.f, acc1 = 0.f, acc2 = 0.f, acc3 = 0.f;
    for (int k = 0; k < MD; k++) {
        float qk = qs[k];
        const float* wrow = Ws + (size_t)k * AD;
        acc0 += qk * wrow[a0];
        acc1 += qk * wrow[a0 + 256];
        acc2 += qk * wrow[a0 + 512];
        acc3 += qk * wrow[a0 + 768];
    }
    g_tq[b * AD + a0]       = acc0;
    g_tq[b * AD + a0 + 256] = acc1;
    g_tq[b * AD + a0 + 512] = acc2;
    g_tq[b * AD + a0 + 768] = acc3;
}

// ---------------------------------------------------------------------------
// Fused big GEMM + tanh + (@v) reduction.
// C-tile = mv[128 rows, :] @ Wh[:, 128 cols]; epilogue computes
// sum_j tanh(c + tq[b, col]) * v[col] per row and atomically adds to logits.
// 128x128 tile, K-step 8, 8x8 register micro-tile, 256 threads.
// A 128-row tile never crosses a batch boundary (512 % 128 == 0).
// ---------------------------------------------------------------------------
__global__ __launch_bounds__(256) void gemm_tanh_kernel(
        const float* __restrict__ A,    // mv flattened [ROWS, MD]
        const float* __restrict__ Wh,   // [MD, AD]
        const float* __restrict__ v) {  // [AD]
    __shared__ float As[8][128];
    __shared__ float Bs[8][128];
    __shared__ float red[128];

    const int tid   = threadIdx.x;
    const int tileM = blockIdx.x * 128;
    const int tileN = blockIdx.y * 128;
    const int tx = tid & 15;
    const int ty = tid >> 4;

    // Global-load assignments (each thread: one float4 of A, one of B per step)
    const int arow = tid >> 1;          // 0..127
    const int acol = (tid & 1) * 4;     // 0 or 4 (k offset)
    const int brow = tid >> 5;          // 0..7   (k)
    const int bcol = (tid & 31) * 4;    // 0..124

    const float* Aptr = A  + (size_t)(tileM + arow) * MD + acol;
    const float* Bptr = Wh + (size_t)brow * AD + tileN + bcol;

    float acc[8][8];
#pragma unroll
    for (int i = 0; i < 8; i++)
#pragma unroll
        for (int j = 0; j < 8; j++) acc[i][j] = 0.f;

    for (int k0 = 0; k0 < MD; k0 += 8) {
        float4 a4 = *reinterpret_cast<const float4*>(Aptr + k0);
        float4 b4 = *reinterpret_cast<const float4*>(Bptr + (size_t)k0 * AD);
        As[acol + 0][arow] = a4.x;
        As[acol + 1][arow] = a4.y;
        As[acol + 2][arow] = a4.z;
        As[acol + 3][arow] = a4.w;
        *reinterpret_cast<float4*>(&Bs[brow][bcol]) = b4;
        __syncthreads();

#pragma unroll
        for (int k = 0; k < 8; k++) {
            float af[8], bf[8];
            *reinterpret_cast<float4*>(&af[0]) =
                *reinterpret_cast<const float4*>(&As[k][ty * 8]);
            *reinterpret_cast<float4*>(&af[4]) =
                *reinterpret_cast<const float4*>(&As[k][ty * 8 + 4]);
            *reinterpret_cast<float4*>(&bf[0]) =
                *reinterpret_cast<const float4*>(&Bs[k][tx * 8]);
            *reinterpret_cast<float4*>(&bf[4]) =
                *reinterpret_cast<const float4*>(&Bs[k][tx * 8 + 4]);
#pragma unroll
            for (int i = 0; i < 8; i++)
#pragma unroll
                for (int j = 0; j < 8; j++) acc[i][j] += af[i] * bf[j];
        }
        __syncthreads();
    }

    // ---- fused epilogue: tanh(c + tq) * v, reduce over columns ----
    if (tid < 128) red[tid] = 0.f;
    __syncthreads();

    const int b = tileM / NN;           // constant per block
    float tqv[8], vv[8];
#pragma unroll
    for (int j = 0; j < 8; j++) {
        int col = tileN + tx * 8 + j;
        tqv[j] = g_tq[b * AD + col];
        vv[j]  = v[col];
    }
#pragma unroll
    for (int i = 0; i < 8; i++) {
        float part = 0.f;
#pragma unroll
        for (int j = 0; j < 8; j++)
            part += tanhf(acc[i][j] + tqv[j]) * vv[j];
        atomicAdd(&red[ty * 8 + i], part);
    }
    __syncthreads();
    if (tid < 128) atomicAdd(&g_logits[tileM + tid], red[tid]);
}

// ---------------------------------------------------------------------------
// Masked softmax over N per batch row (reference semantics incl. no_cells)
// ---------------------------------------------------------------------------
__global__ __launch_bounds__(NN) void softmax_kernel(const int* __restrict__ mask) {
    __shared__ float sdata[NN];
    int b = blockIdx.x, n = threadIdx.x;
    float lg = g_logits[b * NN + n];
    int   m  = mask[b * NN + n];

    int any = __syncthreads_or(m != 0);          // !any == no_cells
    float x = lg + ((any && m == 0) ? -1e30f : 0.0f);

    // max reduce
    sdata[n] = x;
    __syncthreads();
    for (int s = NN / 2; s > 0; s >>= 1) {
        if (n < s) sdata[n] = fmaxf(sdata[n], sdata[n + s]);
        __syncthreads();
    }
    float mx = sdata[0];
    __syncthreads();

    float e = __expf(x - mx);
    sdata[n] = e;
    __syncthreads();
    for (int s = NN / 2; s > 0; s >>= 1) {
        if (n < s) sdata[n] += sdata[n + s];
        __syncthreads();
    }
    float w = e / sdata[0];
    if (!any) w = 0.0f;
    g_weights[b * NN + n] = w;
}

// ---------------------------------------------------------------------------
// context[b, d] = sum_n weights[b, n] * mv[b, n, d]   (memory-bound)
// grid: (d-chunks=4, b=64, n-halves=2); atomicAdd across the two n-halves.
// ---------------------------------------------------------------------------
__global__ __launch_bounds__(256) void context_kernel(const float* __restrict__ mv,
                                                      float* __restrict__ out) {
    __shared__ float ws[256];
    const int b  = blockIdx.y;
    const int d  = blockIdx.x * 256 + threadIdx.x;
    const int n0 = blockIdx.z * 256;

    ws[threadIdx.x] = g_weights[b * NN + n0 + threadIdx.x];
    __syncthreads();

    const float* base = mv + ((size_t)b * NN + n0) * MD + d;
    float acc = 0.f;
#pragma unroll 8
    for (int n = 0; n < 256; n++)
        acc += ws[n] * base[(size_t)n * MD];

    atomicAdd(&out[b * AD + d], acc);
}

// ---------------------------------------------------------------------------
// Launch
// ---------------------------------------------------------------------------
extern "C" void kernel_launch(void* const* d_in, const int* in_sizes, int n_in,
                              void* d_out, int out_size) {
    const float* mv    = (const float*)d_in[0];  // (64, 512, 1024)
    const int*   mask  = (const int*)  d_in[1];  // (64, 512)
    const float* query = (const float*)d_in[2];  // (64, 1024)
    const float* Wh    = (const float*)d_in[3];  // (1024, 1024)
    const float* Ws    = (const float*)d_in[4];  // (1024, 1024)
    const float* v     = (const float*)d_in[5];  // (1024, 1)
    float* out = (float*)d_out;                  // (64, 1024)

    zero_kernel<<<(BB * AD + 255) / 256, 256>>>(out);
    tq_kernel<<<BB, 256>>>(query, Ws);

    dim3 ggrid(ROWS / 128, AD / 128);            // 256 x 8
    gemm_tanh_kernel<<<ggrid, 256>>>(mv, Wh, v);

    softmax_kernel<<<BB, NN>>>(mask);

    dim3 cgrid(AD / 256, BB, 2);                 // 4 x 64 x 2
    context_kernel<<<cgrid, 256>>>(mv, out);
}

// round 6
// speedup vs baseline: 2.3614x; 2.3614x over previous
#include <cuda_runtime.h>
#include <cuda_bf16.h>
#include <cstdint>
#include <math.h>

// ---------------- problem dims ----------------
#define BB   64
#define NN   512
#define MD   1024
#define AD   1024
#define ROWS (BB * NN)          // 32768

// ---------------- GEMM tiling ----------------
#define MT 128                  // M per CTA
#define NT 128                  // N per CTA
#define KC 64                   // K elems per chunk (64 bf16 = 128 B rows)
#define NSEG 3                  // AhBh + AhBl + AlBh
#define NCHUNK (NSEG * MD / KC) // 48

#define STAGE_BYTES 32768       // A 16K + B 16K
#define SMEM_TOTAL  (3 * STAGE_BYTES)

// XOR swizzle for 128-byte rows (conflict-free ldmatrix + cp.async stores)
#define SWZ(x) ((x) ^ (((x) >> 3) & 0x70))

// ---------------- scratch (__device__ globals; no allocs allowed) ----------
__device__ float g_tq[BB * AD];
__device__ float g_logits[ROWS];
__device__ float g_weights[ROWS];
__device__ __nv_bfloat16 g_Ahi[(size_t)ROWS * MD];   // mv hi
__device__ __nv_bfloat16 g_Alo[(size_t)ROWS * MD];   // mv lo
__device__ __nv_bfloat16 g_Bhi[(size_t)AD * MD];     // Wh^T hi  [n][k]
__device__ __nv_bfloat16 g_Blo[(size_t)AD * MD];     // Wh^T lo

// ---------------- PTX helpers (all plain-sm_103-legal) ----------------
__device__ __forceinline__ uint32_t smem_u32(const void* p) {
    uint32_t a;
    asm("{ .reg .u64 t; cvta.to.shared.u64 t, %1; cvt.u32.u64 %0, t; }"
        : "=r"(a) : "l"(p));
    return a;
}
__device__ __forceinline__ void cp16(uint32_t s, const void* g) {
    asm volatile("cp.async.cg.shared.global [%0], [%1], 16;" :: "r"(s), "l"(g));
}
#define CP_COMMIT() asm volatile("cp.async.commit_group;" ::: "memory")
#define CP_WAIT2()  asm volatile("cp.async.wait_group %0;" :: "n"(2) : "memory")

#define LDSM4(r, a) \
    asm volatile("ldmatrix.sync.aligned.m8n8.x4.shared.b16 {%0,%1,%2,%3}, [%4];" \
        : "=r"((r)[0]), "=r"((r)[1]), "=r"((r)[2]), "=r"((r)[3]) : "r"(a))

#define MMA16816(d, a, b0v, b1v) \
    asm volatile("mma.sync.aligned.m16n8k16.row.col.f32.bf16.bf16.f32 " \
        "{%0,%1,%2,%3}, {%4,%5,%6,%7}, {%8,%9}, {%0,%1,%2,%3};" \
        : "+f"((d)[0]), "+f"((d)[1]), "+f"((d)[2]), "+f"((d)[3]) \
        : "r"((a)[0]), "r"((a)[1]), "r"((a)[2]), "r"((a)[3]), \
          "r"(b0v), "r"(b1v))

// ---------------------------------------------------------------------------
// Zero init (logits accumulated by atomics; d_out poisoned by harness)
// ---------------------------------------------------------------------------
__global__ void zero_kernel(float* __restrict__ ctx) {
    int i = blockIdx.x * blockDim.x + threadIdx.x;
    if (i < ROWS) g_logits[i] = 0.0f;
    if (i < BB * AD) ctx[i] = 0.0f;
}

// ---------------------------------------------------------------------------
// fp32 -> bf16 (hi, lo) split of mv
// ---------------------------------------------------------------------------
__global__ __launch_bounds__(256) void convert_mv_kernel(const float* __restrict__ mv) {
    size_t i = ((size_t)blockIdx.x * 256 + threadIdx.x) * 4;
    float4 x = *reinterpret_cast<const float4*>(mv + i);
    __nv_bfloat16 h0 = __float2bfloat16(x.x);
    __nv_bfloat16 h1 = __float2bfloat16(x.y);
    __nv_bfloat16 h2 = __float2bfloat16(x.z);
    __nv_bfloat16 h3 = __float2bfloat16(x.w);
    __nv_bfloat16 l0 = __float2bfloat16(x.x - __bfloat162float(h0));
    __nv_bfloat16 l1 = __float2bfloat16(x.y - __bfloat162float(h1));
    __nv_bfloat16 l2 = __float2bfloat16(x.z - __bfloat162float(h2));
    __nv_bfloat16 l3 = __float2bfloat16(x.w - __bfloat162float(h3));
    __nv_bfloat162* dh = reinterpret_cast<__nv_bfloat162*>(g_Ahi + i);
    __nv_bfloat162* dl = reinterpret_cast<__nv_bfloat162*>(g_Alo + i);
    dh[0] = __nv_bfloat162(h0, h1); dh[1] = __nv_bfloat162(h2, h3);
    dl[0] = __nv_bfloat162(l0, l1); dl[1] = __nv_bfloat162(l2, l3);
}

// ---------------------------------------------------------------------------
// Wh [k][n] -> Wh^T hi/lo bf16 [n][k] via smem tile transpose
// ---------------------------------------------------------------------------
__global__ void whT_convert_kernel(const float* __restrict__ Wh) {
    __shared__ float t[32][33];
    int n0 = blockIdx.x * 32, k0 = blockIdx.y * 32;
    int tx = threadIdx.x, ty = threadIdx.y;          // block (32, 8)
    for (int i = ty; i < 32; i += 8)
        t[i][tx] = Wh[(size_t)(k0 + i) * AD + n0 + tx];
    __syncthreads();
    for (int i = ty; i < 32; i += 8) {
        float x = t[tx][i];                          // Wh[k0+tx][n0+i]
        size_t o = (size_t)(n0 + i) * MD + k0 + tx;  // WhT[n][k]
        __nv_bfloat16 h = __float2bfloat16(x);
        g_Bhi[o] = h;
        g_Blo[o] = __float2bfloat16(x - __bfloat162float(h));
    }
}

// ---------------------------------------------------------------------------
// tq = query @ Ws   (tiny)
// ---------------------------------------------------------------------------
__global__ __launch_bounds__(256) void tq_kernel(const float* __restrict__ q,
                                                 const float* __restrict__ Ws) {
    __shared__ float qs[MD];
    int b = blockIdx.x;
    for (int i = threadIdx.x; i < MD; i += 256) qs[i] = q[b * MD + i];
    __syncthreads();
    int a0 = threadIdx.x;
    float acc0 = 0.f, acc1 = 0.f, acc2 = 0.f, acc3 = 0.f;
    for (int k = 0; k < MD; k++) {
        float qk = qs[k];
        const float* wrow = Ws + (size_t)k * AD;
        acc0 += qk * wrow[a0];
        acc1 += qk * wrow[a0 + 256];
        acc2 += qk * wrow[a0 + 512];
        acc3 += qk * wrow[a0 + 768];
    }
    g_tq[b * AD + a0]       = acc0;
    g_tq[b * AD + a0 + 256] = acc1;
    g_tq[b * AD + a0 + 512] = acc2;
    g_tq[b * AD + a0 + 768] = acc3;
}

// ---------------------------------------------------------------------------
// Big GEMM on HMMA (mma.sync bf16, fp32 accum), 3-term fp32 emulation:
// D = Ah@Bh^T + Ah@Bl^T + Al@Bh^T, fused epilogue logits += sum_n tanh(D+tq)*v
// CTA 128x128, 8 warps (warp tile 64x32), K = 3 segments x 16 chunks of 64.
// 3-stage cp.async pipeline, SW128-swizzled smem, ldmatrix operand fetch.
// ---------------------------------------------------------------------------
__global__ __launch_bounds__(256, 2) void gemm_hmma_kernel(const float* __restrict__ v) {
    extern __shared__ char smem[];
    const uint32_t sb = smem_u32(smem);
    const int tid  = threadIdx.x;
    const int lane = tid & 31;
    const int w    = tid >> 5;
    const int tileN = blockIdx.x * NT;
    const int tileM = blockIdx.y * MT;

    const __nv_bfloat16* Aseg[NSEG] = {
        g_Ahi + (size_t)tileM * MD,
        g_Ahi + (size_t)tileM * MD,
        g_Alo + (size_t)tileM * MD };
    const __nv_bfloat16* Bseg[NSEG] = {
        g_Bhi + (size_t)tileN * MD,
        g_Blo + (size_t)tileN * MD,
        g_Bhi + (size_t)tileN * MD };

    // cp.async per-thread coords: 16B unit cc within 128B row, row group cr
    const int cr = tid >> 3;            // 0..31 (+32 per iter)
    const int cc = tid & 7;             // 0..7

    // ldmatrix per-lane invariants
    const int lrow = lane & 15;         // row within 16-row block
    const int lkb  = (lane >> 4) * 16;  // +16B for k-hi half

    // warp tile position
    const int wm = (w >> 2) * 64;       // 2 m-blocks of 64
    const int wn = (w & 3) * 32;        // 4 n-blocks of 32

    float acc[4][4][4];
#pragma unroll
    for (int i = 0; i < 4; i++)
#pragma unroll
        for (int j = 0; j < 4; j++)
#pragma unroll
            for (int c = 0; c < 4; c++) acc[i][j][c] = 0.f;

    auto issue_copy = [&](int chunk) {
        const int seg = chunk >> 4;
        const int k0  = (chunk & 15) * KC;
        const uint32_t stA = sb + (chunk % 3) * STAGE_BYTES;
        const uint32_t stB = stA + 16384;
        const __nv_bfloat16* Ag = Aseg[seg];
        const __nv_bfloat16* Bg = Bseg[seg];
#pragma unroll
        for (int i = 0; i < 4; i++) {
            const int r = cr + i * 32;
            const uint32_t so = SWZ((uint32_t)(r * 128 + cc * 16));
            cp16(stA + so, Ag + (size_t)r * MD + k0 + cc * 8);
            cp16(stB + so, Bg + (size_t)r * MD + k0 + cc * 8);
        }
    };

    issue_copy(0); CP_COMMIT();
    issue_copy(1); CP_COMMIT();

    for (int c = 0; c < NCHUNK; ++c) {
        if (c + 2 < NCHUNK) issue_copy(c + 2);
        CP_COMMIT();
        CP_WAIT2();
        __syncthreads();

        const uint32_t stA = sb + (c % 3) * STAGE_BYTES;
        const uint32_t stB = stA + 16384;
#pragma unroll
        for (int ks = 0; ks < 4; ks++) {
            const int kb2 = ks * 32 + lkb;     // byte offset in 128B row
            uint32_t a[4][4], b[2][4];
#pragma unroll
            for (int i = 0; i < 4; i++) {
                uint32_t ad = stA + SWZ((uint32_t)((wm + i * 16 + lrow) * 128 + kb2));
                LDSM4(a[i], ad);
            }
#pragma unroll
            for (int j = 0; j < 2; j++) {
                uint32_t ad = stB + SWZ((uint32_t)((wn + j * 16 + lrow) * 128 + kb2));
                LDSM4(b[j], ad);
            }
#pragma unroll
            for (int i = 0; i < 4; i++) {
                MMA16816(acc[i][0], a[i], b[0][0], b[0][2]);
                MMA16816(acc[i][1], a[i], b[0][1], b[0][3]);
                MMA16816(acc[i][2], a[i], b[1][0], b[1][2]);
                MMA16816(acc[i][3], a[i], b[1][1], b[1][3]);
            }
        }
        __syncthreads();
    }

    // ---- fused epilogue: logits[m] += sum_n tanh(acc + tq[b][n]) * v[n] ----
    const int bq = (tileM / NN) * AD;
    const int rq = lane >> 2;            // c-frag row within m16
    const int cq = (lane & 3) * 2;       // c-frag col pair

#pragma unroll
    for (int i = 0; i < 4; i++) {
        float s0 = 0.f, s1 = 0.f;
#pragma unroll
        for (int j = 0; j < 4; j++) {
            const int n0 = tileN + wn + j * 8 + cq;
            const float v0 = v[n0],          v1 = v[n0 + 1];
            const float t0 = g_tq[bq + n0],  t1 = g_tq[bq + n0 + 1];
            s0 += tanhf(acc[i][j][0] + t0) * v0 + tanhf(acc[i][j][1] + t1) * v1;
            s1 += tanhf(acc[i][j][2] + t0) * v0 + tanhf(acc[i][j][3] + t1) * v1;
        }
        s0 += __shfl_xor_sync(0xffffffffu, s0, 1);
        s0 += __shfl_xor_sync(0xffffffffu, s0, 2);
        s1 += __shfl_xor_sync(0xffffffffu, s1, 1);
        s1 += __shfl_xor_sync(0xffffffffu, s1, 2);
        if ((lane & 3) == 0) {
            const int m0 = tileM + wm + i * 16 + rq;
            atomicAdd(&g_logits[m0],     s0);
            atomicAdd(&g_logits[m0 + 8], s1);
        }
    }
}

// ---------------------------------------------------------------------------
// Masked softmax (reference semantics incl. fully-masked rows)
// ---------------------------------------------------------------------------
__global__ __launch_bounds__(NN) void softmax_kernel(const int* __restrict__ mask) {
    __shared__ float sdata[NN];
    int b = blockIdx.x, n = threadIdx.x;
    float lg = g_logits[b * NN + n];
    int   m  = mask[b * NN + n];

    int any = __syncthreads_or(m != 0);
    float x = lg + ((any && m == 0) ? -1e30f : 0.0f);

    sdata[n] = x;
    __syncthreads();
    for (int s = NN / 2; s > 0; s >>= 1) {
        if (n < s) sdata[n] = fmaxf(sdata[n], sdata[n + s]);
        __syncthreads();
    }
    float mx = sdata[0];
    __syncthreads();

    float e = __expf(x - mx);
    sdata[n] = e;
    __syncthreads();
    for (int s = NN / 2; s > 0; s >>= 1) {
        if (n < s) sdata[n] += sdata[n + s];
        __syncthreads();
    }
    float wgt = e / sdata[0];
    if (!any) wgt = 0.0f;
    g_weights[b * NN + n] = wgt;
}

// ---------------------------------------------------------------------------
// context[b, d] = sum_n weights[b, n] * mv[b, n, d]
// ---------------------------------------------------------------------------
__global__ __launch_bounds__(256) void context_kernel(const float* __restrict__ mv,
                                                      float* __restrict__ out) {
    __shared__ float ws[256];
    const int b  = blockIdx.y;
    const int d  = blockIdx.x * 256 + threadIdx.x;
    const int n0 = blockIdx.z * 256;

    ws[threadIdx.x] = g_weights[b * NN + n0 + threadIdx.x];
    __syncthreads();

    const float* base = mv + ((size_t)b * NN + n0) * MD + d;
    float acc = 0.f;
#pragma unroll 8
    for (int n = 0; n < 256; n++)
        acc += ws[n] * base[(size_t)n * MD];

    atomicAdd(&out[b * AD + d], acc);
}

// ---------------------------------------------------------------------------
extern "C" void kernel_launch(void* const* d_in, const int* in_sizes, int n_in,
                              void* d_out, int out_size) {
    const float* mv    = (const float*)d_in[0];  // (64, 512, 1024)
    const int*   mask  = (const int*)  d_in[1];  // (64, 512)
    const float* query = (const float*)d_in[2];  // (64, 1024)
    const float* Wh    = (const float*)d_in[3];  // (1024, 1024)
    const float* Ws    = (const float*)d_in[4];  // (1024, 1024)
    const float* v     = (const float*)d_in[5];  // (1024, 1)
    float* out = (float*)d_out;                  // (64, 1024)

    cudaFuncSetAttribute(gemm_hmma_kernel,
                         cudaFuncAttributeMaxDynamicSharedMemorySize, SMEM_TOTAL);

    zero_kernel<<<(BB * AD + 255) / 256, 256>>>(out);
    convert_mv_kernel<<<(int)((size_t)ROWS * MD / 1024), 256>>>(mv);
    whT_convert_kernel<<<dim3(32, 32), dim3(32, 8)>>>(Wh);
    tq_kernel<<<BB, 256>>>(query, Ws);

    // x = N tiles (fast) so a wave shares A tiles through L2
    gemm_hmma_kernel<<<dim3(AD / NT, ROWS / MT), 256, SMEM_TOTAL>>>(v);

    softmax_kernel<<<BB, NN>>>(mask);
    context_kernel<<<dim3(AD / 256, BB, 2), 256>>>(mv, out);
}

// round 8
// speedup vs baseline: 4.4156x; 1.8699x over previous
#include <cuda_runtime.h>
#include <cuda_fp16.h>
#include <cstdint>
#include <math.h>

// ---------------- problem dims ----------------
#define BB   64
#define NN   512
#define MD   1024
#define AD   1024
#define ROWS (BB * NN)          // 32768

// ---------------- GEMM tiling ----------------
#define MT 128                  // M per CTA
#define NT 128                  // N per CTA
#define KC 64                   // K elems per chunk (64 fp16 = 128 B rows)
#define NCHUNK (MD / KC)        // 16

// stage: A 16K | Bh 16K | Bl 16K
#define ST_A  0
#define ST_BH 16384
#define ST_BL 32768
#define STAGE_BYTES 49152
#define SMEM_TOTAL  (2 * STAGE_BYTES)   // 96 KB, 2 CTAs/SM

// XOR swizzle for 128-byte rows (conflict-free ldmatrix + cp.async stores)
#define SWZ(x) ((x) ^ (((x) >> 3) & 0x70))

// ---------------- scratch (__device__ globals; no allocs allowed) ----------
__device__ float g_tq[BB * AD];
__device__ float g_logits[ROWS];
__device__ float g_weights[ROWS];
__device__ __half g_Ah[(size_t)ROWS * MD];   // mv rounded to fp16
__device__ __half g_Bh[(size_t)AD * MD];     // Wh^T hi  [n][k]
__device__ __half g_Bl[(size_t)AD * MD];     // Wh^T lo residual

// ---------------- PTX helpers (plain-sm_103-legal) ----------------
__device__ __forceinline__ uint32_t smem_u32(const void* p) {
    uint32_t a;
    asm("{ .reg .u64 t; cvta.to.shared.u64 t, %1; cvt.u32.u64 %0, t; }"
        : "=r"(a) : "l"(p));
    return a;
}
__device__ __forceinline__ void cp16(uint32_t s, const void* g) {
    asm volatile("cp.async.cg.shared.global [%0], [%1], 16;" :: "r"(s), "l"(g));
}
#define CP_COMMIT() asm volatile("cp.async.commit_group;" ::: "memory")
#define CP_WAIT1()  asm volatile("cp.async.wait_group %0;" :: "n"(1) : "memory")

#define LDSM4(r, a) \
    asm volatile("ldmatrix.sync.aligned.m8n8.x4.shared.b16 {%0,%1,%2,%3}, [%4];" \
        : "=r"((r)[0]), "=r"((r)[1]), "=r"((r)[2]), "=r"((r)[3]) : "r"(a))

#define MMA16816(d, a, b0v, b1v) \
    asm volatile("mma.sync.aligned.m16n8k16.row.col.f32.f16.f16.f32 " \
        "{%0,%1,%2,%3}, {%4,%5,%6,%7}, {%8,%9}, {%0,%1,%2,%3};" \
        : "+f"((d)[0]), "+f"((d)[1]), "+f"((d)[2]), "+f"((d)[3]) \
        : "r"((a)[0]), "r"((a)[1]), "r"((a)[2]), "r"((a)[3]), \
          "r"(b0v), "r"(b1v))

// ---------------------------------------------------------------------------
// Zero init: logits, tq (both atomic-accumulated), d_out (poisoned)
// ---------------------------------------------------------------------------
__global__ void zero_kernel(float* __restrict__ ctx) {
    int i = blockIdx.x * blockDim.x + threadIdx.x;   // 0 .. 65535
    if (i < ROWS) g_logits[i] = 0.0f;
    if (i < BB * AD) { g_tq[i] = 0.0f; ctx[i] = 0.0f; }
}

// ---------------------------------------------------------------------------
// fp32 -> fp16 round of mv (single rounding; error budget ~1e-4 in logits)
// ---------------------------------------------------------------------------
__global__ __launch_bounds__(256) void convert_mv_kernel(const float* __restrict__ mv) {
    size_t i = ((size_t)blockIdx.x * 256 + threadIdx.x) * 4;
    float4 x = *reinterpret_cast<const float4*>(mv + i);
    __half2* d = reinterpret_cast<__half2*>(g_Ah + i);
    d[0] = __floats2half2_rn(x.x, x.y);
    d[1] = __floats2half2_rn(x.z, x.w);
}

// ---------------------------------------------------------------------------
// Wh [k][n] -> Wh^T hi/lo fp16 [n][k] via smem tile transpose (exact split)
// ---------------------------------------------------------------------------
__global__ void whT_convert_kernel(const float* __restrict__ Wh) {
    __shared__ float t[32][33];
    int n0 = blockIdx.x * 32, k0 = blockIdx.y * 32;
    int tx = threadIdx.x, ty = threadIdx.y;          // block (32, 8)
    for (int i = ty; i < 32; i += 8)
        t[i][tx] = Wh[(size_t)(k0 + i) * AD + n0 + tx];
    __syncthreads();
    for (int i = ty; i < 32; i += 8) {
        float x = t[tx][i];                          // Wh[k0+tx][n0+i]
        size_t o = (size_t)(n0 + i) * MD + k0 + tx;  // WhT[n][k]
        __half h = __float2half_rn(x);
        g_Bh[o] = h;
        g_Bl[o] = __float2half_rn(x - __half2float(h));
    }
}

// ---------------------------------------------------------------------------
// tq = query @ Ws, split-K: grid (16 k-chunks, 64 b), atomicAdd accumulate.
// ---------------------------------------------------------------------------
__global__ __launch_bounds__(256) void tq_kernel(const float* __restrict__ q,
                                                 const float* __restrict__ Ws) {
    __shared__ float qs[64];
    const int b  = blockIdx.y;
    const int k0 = blockIdx.x * 64;
    if (threadIdx.x < 64) qs[threadIdx.x] = q[b * MD + k0 + threadIdx.x];
    __syncthreads();

    const int a0 = threadIdx.x;          // cols a0, a0+256, a0+512, a0+768
    float acc0 = 0.f, acc1 = 0.f, acc2 = 0.f, acc3 = 0.f;
#pragma unroll 8
    for (int k = 0; k < 64; k++) {
        float qk = qs[k];
        const float* wrow = Ws + (size_t)(k0 + k) * AD;
        acc0 += qk * wrow[a0];
        acc1 += qk * wrow[a0 + 256];
        acc2 += qk * wrow[a0 + 512];
        acc3 += qk * wrow[a0 + 768];
    }
    atomicAdd(&g_tq[b * AD + a0],       acc0);
    atomicAdd(&g_tq[b * AD + a0 + 256], acc1);
    atomicAdd(&g_tq[b * AD + a0 + 512], acc2);
    atomicAdd(&g_tq[b * AD + a0 + 768], acc3);
}

// ---------------------------------------------------------------------------
// Big GEMM on HMMA fp16 (fp32 accum), 2-term emulation:
// D = Ah@Bh^T + Ah@Bl^T  (A rounded once; B exactly split)
// Fused epilogue: logits[m] += sum_n tanh(D + tq) * v[n].
// CTA 128x128, 8 warps (warp tile 64x32), 16 K-chunks of 64, 2-stage cp.async.
// A tile loaded ONCE per chunk, consumed by both B terms.
// ---------------------------------------------------------------------------
__global__ __launch_bounds__(256, 2) void gemm_hmma_kernel(const float* __restrict__ v) {
    extern __shared__ char smem[];
    const uint32_t sb = smem_u32(smem);
    const int tid  = threadIdx.x;
    const int lane = tid & 31;
    const int w    = tid >> 5;
    const int tileN = blockIdx.x * NT;
    const int tileM = blockIdx.y * MT;

    const __half* Ag  = g_Ah + (size_t)tileM * MD;
    const __half* Bhg = g_Bh + (size_t)tileN * MD;
    const __half* Blg = g_Bl + (size_t)tileN * MD;

    // cp.async per-thread coords
    const int cr = tid >> 3;            // 0..31 (+32 per rep)
    const int cc = tid & 7;             // 16B unit in 128B row

    // ldmatrix invariants
    const int lrow = lane & 15;
    const int lkb  = (lane >> 4) * 16;

    // warp tile position
    const int wm = (w >> 2) * 64;
    const int wn = (w & 3) * 32;

    float acc[4][4][4];
#pragma unroll
    for (int i = 0; i < 4; i++)
#pragma unroll
        for (int j = 0; j < 4; j++)
#pragma unroll
            for (int c = 0; c < 4; c++) acc[i][j][c] = 0.f;

    auto issue_copy = [&](int chunk) {
        const int k0 = chunk * KC;
        const uint32_t st = sb + (chunk & 1) * STAGE_BYTES;
#pragma unroll
        for (int i = 0; i < 4; i++) {
            const int r = cr + i * 32;
            const uint32_t so = SWZ((uint32_t)(r * 128 + cc * 16));
            const size_t go = (size_t)r * MD + k0 + cc * 8;
            cp16(st + ST_A  + so, Ag  + go);
            cp16(st + ST_BH + so, Bhg + go);
            cp16(st + ST_BL + so, Blg + go);
        }
    };

    issue_copy(0); CP_COMMIT();

    for (int c = 0; c < NCHUNK; ++c) {
        if (c + 1 < NCHUNK) issue_copy(c + 1);
        CP_COMMIT();
        CP_WAIT1();
        __syncthreads();

        const uint32_t st = sb + (c & 1) * STAGE_BYTES;
#pragma unroll
        for (int ks = 0; ks < 4; ks++) {
            const int kb2 = ks * 32 + lkb;
            uint32_t a[4][4], bh[2][4], bl[2][4];
#pragma unroll
            for (int i = 0; i < 4; i++) {
                uint32_t ad = st + ST_A + SWZ((uint32_t)((wm + i * 16 + lrow) * 128 + kb2));
                LDSM4(a[i], ad);
            }
#pragma unroll
            for (int j = 0; j < 2; j++) {
                uint32_t r = (uint32_t)((wn + j * 16 + lrow) * 128 + kb2);
                uint32_t adh = st + ST_BH + SWZ(r);
                uint32_t adl = st + ST_BL + SWZ(r);
                LDSM4(bh[j], adh);
                LDSM4(bl[j], adl);
            }
#pragma unroll
            for (int i = 0; i < 4; i++) {
                MMA16816(acc[i][0], a[i], bh[0][0], bh[0][2]);
                MMA16816(acc[i][1], a[i], bh[0][1], bh[0][3]);
                MMA16816(acc[i][2], a[i], bh[1][0], bh[1][2]);
                MMA16816(acc[i][3], a[i], bh[1][1], bh[1][3]);
                MMA16816(acc[i][0], a[i], bl[0][0], bl[0][2]);
                MMA16816(acc[i][1], a[i], bl[0][1], bl[0][3]);
                MMA16816(acc[i][2], a[i], bl[1][0], bl[1][2]);
                MMA16816(acc[i][3], a[i], bl[1][1], bl[1][3]);
            }
        }
        __syncthreads();
    }

    // ---- fused epilogue: logits[m] += sum_n tanh(acc + tq[b][n]) * v[n] ----
    const int bq = (tileM / NN) * AD;
    const int rq = lane >> 2;
    const int cq = (lane & 3) * 2;

#pragma unroll
    for (int i = 0; i < 4; i++) {
        float s0 = 0.f, s1 = 0.f;
#pragma unroll
        for (int j = 0; j < 4; j++) {
            const int n0 = tileN + wn + j * 8 + cq;
            const float v0 = v[n0],          v1 = v[n0 + 1];
            const float t0 = g_tq[bq + n0],  t1 = g_tq[bq + n0 + 1];
            s0 += tanhf(acc[i][j][0] + t0) * v0 + tanhf(acc[i][j][1] + t1) * v1;
            s1 += tanhf(acc[i][j][2] + t0) * v0 + tanhf(acc[i][j][3] + t1) * v1;
        }
        s0 += __shfl_xor_sync(0xffffffffu, s0, 1);
        s0 += __shfl_xor_sync(0xffffffffu, s0, 2);
        s1 += __shfl_xor_sync(0xffffffffu, s1, 1);
        s1 += __shfl_xor_sync(0xffffffffu, s1, 2);
        if ((lane & 3) == 0) {
            const int m0 = tileM + wm + i * 16 + rq;
            atomicAdd(&g_logits[m0],     s0);
            atomicAdd(&g_logits[m0 + 8], s1);
        }
    }
}

// ---------------------------------------------------------------------------
// Masked softmax (reference semantics incl. fully-masked rows)
// ---------------------------------------------------------------------------
__global__ __launch_bounds__(NN) void softmax_kernel(const int* __restrict__ mask) {
    __shared__ float sdata[NN];
    int b = blockIdx.x, n = threadIdx.x;
    float lg = g_logits[b * NN + n];
    int   m  = mask[b * NN + n];

    int any = __syncthreads_or(m != 0);
    float x = lg + ((any && m == 0) ? -1e30f : 0.0f);

    sdata[n] = x;
    __syncthreads();
    for (int s = NN / 2; s > 0; s >>= 1) {
        if (n < s) sdata[n] = fmaxf(sdata[n], sdata[n + s]);
        __syncthreads();
    }
    float mx = sdata[0];
    __syncthreads();

    float e = __expf(x - mx);
    sdata[n] = e;
    __syncthreads();
    for (int s = NN / 2; s > 0; s >>= 1) {
        if (n < s) sdata[n] += sdata[n + s];
        __syncthreads();
    }
    float wgt = e / sdata[0];
    if (!any) wgt = 0.0f;
    g_weights[b * NN + n] = wgt;
}

// ---------------------------------------------------------------------------
// context[b, d] = sum_n weights[b, n] * mv[b, n, d]
// ---------------------------------------------------------------------------
__global__ __launch_bounds__(256) void context_kernel(const float* __restrict__ mv,
                                                      float* __restrict__ out) {
    __shared__ float ws[256];
    const int b  = blockIdx.y;
    const int d  = blockIdx.x * 256 + threadIdx.x;
    const int n0 = blockIdx.z * 256;

    ws[threadIdx.x] = g_weights[b * NN + n0 + threadIdx.x];
    __syncthreads();

    const float* base = mv + ((size_t)b * NN + n0) * MD + d;
    float acc = 0.f;
#pragma unroll 8
    for (int n = 0; n < 256; n++)
        acc += ws[n] * base[(size_t)n * MD];

    atomicAdd(&out[b * AD + d], acc);
}

// ---------------------------------------------------------------------------
extern "C" void kernel_launch(void* const* d_in, const int* in_sizes, int n_in,
                              void* d_out, int out_size) {
    const float* mv    = (const float*)d_in[0];  // (64, 512, 1024)
    const int*   mask  = (const int*)  d_in[1];  // (64, 512)
    const float* query = (const float*)d_in[2];  // (64, 1024)
    const float* Wh    = (const float*)d_in[3];  // (1024, 1024)
    const float* Ws    = (const float*)d_in[4];  // (1024, 1024)
    const float* v     = (const float*)d_in[5];  // (1024, 1)
    float* out = (float*)d_out;                  // (64, 1024)

    cudaFuncSetAttribute(gemm_hmma_kernel,
                         cudaFuncAttributeMaxDynamicSharedMemorySize, SMEM_TOTAL);

    zero_kernel<<<(BB * AD + 255) / 256, 256>>>(out);
    convert_mv_kernel<<<(int)((size_t)ROWS * MD / 1024), 256>>>(mv);
    whT_convert_kernel<<<dim3(32, 32), dim3(32, 8)>>>(Wh);
    tq_kernel<<<dim3(16, BB), 256>>>(query, Ws);

    // x = N tiles (fast) so a wave shares A tiles through L2
    gemm_hmma_kernel<<<dim3(AD / NT, ROWS / MT), 256, SMEM_TOTAL>>>(v);

    softmax_kernel<<<BB, NN>>>(mask);
    context_kernel<<<dim3(AD / 256, BB, 2), 256>>>(mv, out);
}

// round 11
// speedup vs baseline: 6.7055x; 1.5186x over previous
#include <cuda_runtime.h>
#include <cuda_fp16.h>
#include <cstdint>
#include <math.h>

// ---------------- problem dims ----------------
#define BB   64
#define NN   512
#define MD   1024
#define AD   1024
#define ROWS (BB * NN)          // 32768

// ---------------- GEMM tiling ----------------
#define MT 128                  // M per CTA
#define NT 128                  // N per CTA
#define KC 64                   // K elems per chunk (64 fp16 = 128 B rows)
#define NCHUNK (MD / KC)        // 16

// stage: A 16K | B 16K   (single-term fp16: both operands rounded once)
#define ST_A  0
#define ST_B  16384
#define STAGE_BYTES 32768
#define NSTAGE 3
#define SMEM_TOTAL (NSTAGE * STAGE_BYTES)   // 96 KB, 2 CTAs/SM

// XOR swizzle for 128-byte rows (conflict-free ldmatrix + cp.async stores)
#define SWZ(x) ((x) ^ (((x) >> 3) & 0x70))

// ---------------- scratch (__device__ globals; no allocs allowed) ----------
__device__ float g_tq[BB * AD];
__device__ float g_logits[ROWS];
__device__ float g_weights[ROWS];
__device__ __half g_Ah[(size_t)ROWS * MD];   // mv rounded to fp16
__device__ __half g_Bh[(size_t)AD * MD];     // Wh^T rounded to fp16, [n][k]

// ---------------- PTX helpers (plain-sm_103-legal) ----------------
__device__ __forceinline__ uint32_t smem_u32(const void* p) {
    uint32_t a;
    asm("{ .reg .u64 t; cvta.to.shared.u64 t, %1; cvt.u32.u64 %0, t; }"
        : "=r"(a) : "l"(p));
    return a;
}
__device__ __forceinline__ void cp16(uint32_t s, const void* g) {
    asm volatile("cp.async.cg.shared.global [%0], [%1], 16;" :: "r"(s), "l"(g));
}
#define CP_COMMIT() asm volatile("cp.async.commit_group;" ::: "memory")
#define CP_WAIT2()  asm volatile("cp.async.wait_group %0;" :: "n"(2) : "memory")

#define LDSM4(r, a) \
    asm volatile("ldmatrix.sync.aligned.m8n8.x4.shared.b16 {%0,%1,%2,%3}, [%4];" \
        : "=r"((r)[0]), "=r"((r)[1]), "=r"((r)[2]), "=r"((r)[3]) : "r"(a))

#define MMA16816(d, a, b0v, b1v) \
    asm volatile("mma.sync.aligned.m16n8k16.row.col.f32.f16.f16.f32 " \
        "{%0,%1,%2,%3}, {%4,%5,%6,%7}, {%8,%9}, {%0,%1,%2,%3};" \
        : "+f"((d)[0]), "+f"((d)[1]), "+f"((d)[2]), "+f"((d)[3]) \
        : "r"((a)[0]), "r"((a)[1]), "r"((a)[2]), "r"((a)[3]), \
          "r"(b0v), "r"(b1v))

// ---------------------------------------------------------------------------
// Zero init: logits, tq (both atomic-accumulated), d_out (poisoned)
// ---------------------------------------------------------------------------
__global__ void zero_kernel(float* __restrict__ ctx) {
    int i = blockIdx.x * blockDim.x + threadIdx.x;   // 0 .. 65535
    if (i < ROWS) g_logits[i] = 0.0f;
    if (i < BB * AD) { g_tq[i] = 0.0f; ctx[i] = 0.0f; }
}

// ---------------------------------------------------------------------------
// fp32 -> fp16 round of mv
// ---------------------------------------------------------------------------
__global__ __launch_bounds__(256) void convert_mv_kernel(const float* __restrict__ mv) {
    size_t i = ((size_t)blockIdx.x * 256 + threadIdx.x) * 4;
    float4 x = *reinterpret_cast<const float4*>(mv + i);
    __half2* d = reinterpret_cast<__half2*>(g_Ah + i);
    d[0] = __floats2half2_rn(x.x, x.y);
    d[1] = __floats2half2_rn(x.z, x.w);
}

// ---------------------------------------------------------------------------
// Wh [k][n] -> Wh^T fp16 [n][k] via smem tile transpose
// ---------------------------------------------------------------------------
__global__ void whT_convert_kernel(const float* __restrict__ Wh) {
    __shared__ float t[32][33];
    int n0 = blockIdx.x * 32, k0 = blockIdx.y * 32;
    int tx = threadIdx.x, ty = threadIdx.y;          // block (32, 8)
    for (int i = ty; i < 32; i += 8)
        t[i][tx] = Wh[(size_t)(k0 + i) * AD + n0 + tx];
    __syncthreads();
    for (int i = ty; i < 32; i += 8) {
        float x = t[tx][i];                          // Wh[k0+tx][n0+i]
        g_Bh[(size_t)(n0 + i) * MD + k0 + tx] = __float2half_rn(x);
    }
}

// ---------------------------------------------------------------------------
// tq = query @ Ws, split-K: grid (16 k-chunks, 64 b), atomicAdd accumulate.
// ---------------------------------------------------------------------------
__global__ __launch_bounds__(256) void tq_kernel(const float* __restrict__ q,
                                                 const float* __restrict__ Ws) {
    __shared__ float qs[64];
    const int b  = blockIdx.y;
    const int k0 = blockIdx.x * 64;
    if (threadIdx.x < 64) qs[threadIdx.x] = q[b * MD + k0 + threadIdx.x];
    __syncthreads();

    const int a0 = threadIdx.x;          // cols a0, a0+256, a0+512, a0+768
    float acc0 = 0.f, acc1 = 0.f, acc2 = 0.f, acc3 = 0.f;
#pragma unroll 8
    for (int k = 0; k < 64; k++) {
        float qk = qs[k];
        const float* wrow = Ws + (size_t)(k0 + k) * AD;
        acc0 += qk * wrow[a0];
        acc1 += qk * wrow[a0 + 256];
        acc2 += qk * wrow[a0 + 512];
        acc3 += qk * wrow[a0 + 768];
    }
    atomicAdd(&g_tq[b * AD + a0],       acc0);
    atomicAdd(&g_tq[b * AD + a0 + 256], acc1);
    atomicAdd(&g_tq[b * AD + a0 + 512], acc2);
    atomicAdd(&g_tq[b * AD + a0 + 768], acc3);
}

// ---------------------------------------------------------------------------
// Big GEMM on HMMA fp16 (fp32 accum), single-term: D = Ah @ Bh^T.
// Fused epilogue: logits[m] += sum_n tanh(D + tq) * v[n].
// CTA 128x128, 8 warps (warp tile 64x32), 16 K-chunks of 64,
// 3-stage cp.async pipeline, SW128-swizzled smem, ldmatrix operand fetch.
// ---------------------------------------------------------------------------
__global__ __launch_bounds__(256, 2) void gemm_hmma_kernel(const float* __restrict__ v) {
    extern __shared__ char smem[];
    const uint32_t sb = smem_u32(smem);
    const int tid  = threadIdx.x;
    const int lane = tid & 31;
    const int w    = tid >> 5;
    const int tileN = blockIdx.x * NT;
    const int tileM = blockIdx.y * MT;

    const __half* Ag = g_Ah + (size_t)tileM * MD;
    const __half* Bg = g_Bh + (size_t)tileN * MD;

    // cp.async per-thread coords
    const int cr = tid >> 3;            // 0..31 (+32 per rep)
    const int cc = tid & 7;             // 16B unit in 128B row

    // ldmatrix invariants
    const int lrow = lane & 15;
    const int lkb  = (lane >> 4) * 16;

    // warp tile position
    const int wm = (w >> 2) * 64;
    const int wn = (w & 3) * 32;

    float acc[4][4][4];
#pragma unroll
    for (int i = 0; i < 4; i++)
#pragma unroll
        for (int j = 0; j < 4; j++)
#pragma unroll
            for (int c = 0; c < 4; c++) acc[i][j][c] = 0.f;

    auto issue_copy = [&](int chunk) {
        const int k0 = chunk * KC;
        const uint32_t st = sb + (chunk % NSTAGE) * STAGE_BYTES;
#pragma unroll
        for (int i = 0; i < 4; i++) {
            const int r = cr + i * 32;
            const uint32_t so = SWZ((uint32_t)(r * 128 + cc * 16));
            const size_t go = (size_t)r * MD + k0 + cc * 8;
            cp16(st + ST_A + so, Ag + go);
            cp16(st + ST_B + so, Bg + go);
        }
    };

    issue_copy(0); CP_COMMIT();
    issue_copy(1); CP_COMMIT();

    for (int c = 0; c < NCHUNK; ++c) {
        if (c + 2 < NCHUNK) issue_copy(c + 2);
        CP_COMMIT();
        CP_WAIT2();
        __syncthreads();

        const uint32_t st = sb + (c % NSTAGE) * STAGE_BYTES;
#pragma unroll
        for (int ks = 0; ks < 4; ks++) {
            const int kb2 = ks * 32 + lkb;
            uint32_t a[4][4], b[2][4];
#pragma unroll
            for (int i = 0; i < 4; i++) {
                uint32_t ad = st + ST_A + SWZ((uint32_t)((wm + i * 16 + lrow) * 128 + kb2));
                LDSM4(a[i], ad);
            }
#pragma unroll
            for (int j = 0; j < 2; j++) {
                uint32_t ad = st + ST_B + SWZ((uint32_t)((wn + j * 16 + lrow) * 128 + kb2));
                LDSM4(b[j], ad);
            }
#pragma unroll
            for (int i = 0; i < 4; i++) {
                MMA16816(acc[i][0], a[i], b[0][0], b[0][2]);
                MMA16816(acc[i][1], a[i], b[0][1], b[0][3]);
                MMA16816(acc[i][2], a[i], b[1][0], b[1][2]);
                MMA16816(acc[i][3], a[i], b[1][1], b[1][3]);
            }
        }
        __syncthreads();
    }

    // ---- fused epilogue: logits[m] += sum_n tanh(acc + tq[b][n]) * v[n] ----
    const int bq = (tileM / NN) * AD;
    const int rq = lane >> 2;
    const int cq = (lane & 3) * 2;

#pragma unroll
    for (int i = 0; i < 4; i++) {
        float s0 = 0.f, s1 = 0.f;
#pragma unroll
        for (int j = 0; j < 4; j++) {
            const int n0 = tileN + wn + j * 8 + cq;
            const float v0 = v[n0],          v1 = v[n0 + 1];
            const float t0 = g_tq[bq + n0],  t1 = g_tq[bq + n0 + 1];
            s0 += tanhf(acc[i][j][0] + t0) * v0 + tanhf(acc[i][j][1] + t1) * v1;
            s1 += tanhf(acc[i][j][2] + t0) * v0 + tanhf(acc[i][j][3] + t1) * v1;
        }
        s0 += __shfl_xor_sync(0xffffffffu, s0, 1);
        s0 += __shfl_xor_sync(0xffffffffu, s0, 2);
        s1 += __shfl_xor_sync(0xffffffffu, s1, 1);
        s1 += __shfl_xor_sync(0xffffffffu, s1, 2);
        if ((lane & 3) == 0) {
            const int m0 = tileM + wm + i * 16 + rq;
            atomicAdd(&g_logits[m0],     s0);
            atomicAdd(&g_logits[m0 + 8], s1);
        }
    }
}

// ---------------------------------------------------------------------------
// Masked softmax (reference semantics incl. fully-masked rows)
// ---------------------------------------------------------------------------
__global__ __launch_bounds__(NN) void softmax_kernel(const int* __restrict__ mask) {
    __shared__ float sdata[NN];
    int b = blockIdx.x, n = threadIdx.x;
    float lg = g_logits[b * NN + n];
    int   m  = mask[b * NN + n];

    int any = __syncthreads_or(m != 0);
    float x = lg + ((any && m == 0) ? -1e30f : 0.0f);

    sdata[n] = x;
    __syncthreads();
    for (int s = NN / 2; s > 0; s >>= 1) {
        if (n < s) sdata[n] = fmaxf(sdata[n], sdata[n + s]);
        __syncthreads();
    }
    float mx = sdata[0];
    __syncthreads();

    float e = __expf(x - mx);
    sdata[n] = e;
    __syncthreads();
    for (int s = NN / 2; s > 0; s >>= 1) {
        if (n < s) sdata[n] += sdata[n + s];
        __syncthreads();
    }
    float wgt = e / sdata[0];
    if (!any) wgt = 0.0f;
    g_weights[b * NN + n] = wgt;
}

// ---------------------------------------------------------------------------
// context[b, d] = sum_n weights[b, n] * mv[b, n, d]   (fp32 mv, full accuracy)
// ---------------------------------------------------------------------------
__global__ __launch_bounds__(256) void context_kernel(const float* __restrict__ mv,
                                                      float* __restrict__ out) {
    __shared__ float ws[256];
    const int b  = blockIdx.y;
    const int d  = blockIdx.x * 256 + threadIdx.x;
    const int n0 = blockIdx.z * 256;

    ws[threadIdx.x] = g_weights[b * NN + n0 + threadIdx.x];
    __syncthreads();

    const float* base = mv + ((size_t)b * NN + n0) * MD + d;
    float acc = 0.f;
#pragma unroll 8
    for (int n = 0; n < 256; n++)
        acc += ws[n] * base[(size_t)n * MD];

    atomicAdd(&out[b * AD + d], acc);
}

// ---------------------------------------------------------------------------
extern "C" void kernel_launch(void* const* d_in, const int* in_sizes, int n_in,
                              void* d_out, int out_size) {
    const float* mv    = (const float*)d_in[0];  // (64, 512, 1024)
    const int*   mask  = (const int*)  d_in[1];  // (64, 512)
    const float* query = (const float*)d_in[2];  // (64, 1024)
    const float* Wh    = (const float*)d_in[3];  // (1024, 1024)
    const float* Ws    = (const float*)d_in[4];  // (1024, 1024)
    const float* v     = (const float*)d_in[5];  // (1024, 1)
    float* out = (float*)d_out;                  // (64, 1024)

    cudaFuncSetAttribute(gemm_hmma_kernel,
                         cudaFuncAttributeMaxDynamicSharedMemorySize, SMEM_TOTAL);

    zero_kernel<<<(BB * AD + 255) / 256, 256>>>(out);
    convert_mv_kernel<<<(int)((size_t)ROWS * MD / 1024), 256>>>(mv);
    whT_convert_kernel<<<dim3(32, 32), dim3(32, 8)>>>(Wh);
    tq_kernel<<<dim3(16, BB), 256>>>(query, Ws);

    // x = N tiles (fast) so a wave shares A tiles through L2
    gemm_hmma_kernel<<<dim3(AD / NT, ROWS / MT), 256, SMEM_TOTAL>>>(v);

    softmax_kernel<<<BB, NN>>>(mask);
    context_kernel<<<dim3(AD / 256, BB, 2), 256>>>(mv, out);
}